// round 16
// baseline (speedup 1.0000x reference)
#include <cuda_runtime.h>
#include <cuda_fp16.h>
#include <cstdint>

#define DIN   4096
#define DOUT  4096
#define MROWS 16384
#define RNK   64

#define BM 128
#define BN 256
#define BK 64
#define PADK 72                        // fp16 elems per smem row (144B), ldmatrix conflict-free
#define XT_BYTES (BM*PADK*2)           // 18432 B
#define WT_BYTES (BN*PADK*2)           // 36864 B
#define STG_BYTES (XT_BYTES + WT_BYTES)    // 55296 B per stage
#define NSTAGE 3
#define NIT_MAIN (DIN/BK)              // 64
#define NIT (NIT_MAIN + 1)             // 65: 64 main + 1 LoRA (fp16 z single limb)

// ---------------- scratch (static device globals; no allocation) ----------------
__device__ __half g_Whi[(size_t)DOUT*DIN];     // fp16(W)
__device__ __half g_Xhi[(size_t)MROWS*DIN];    // fp16(x)
__device__ __half g_Bs [(size_t)DOUT*RNK];     // fp16(2*B)  (SCALE folded)
__device__ __half g_Zhi[(size_t)MROWS*RNK];    // fp16(masked z)

// ---------------- PTX helpers ----------------
__device__ __forceinline__ uint32_t sptr(const void* p) {
    return (uint32_t)__cvta_generic_to_shared(p);
}
__device__ __forceinline__ void cp16s(uint32_t dst, const void* src) {
    asm volatile("cp.async.cg.shared.global [%0], [%1], 16;" :: "r"(dst), "l"(src));
}
__device__ __forceinline__ void cp_commit() { asm volatile("cp.async.commit_group;" ::); }
template <int N> __device__ __forceinline__ void cp_wait() {
    asm volatile("cp.async.wait_group %0;" :: "n"(N));
}
__device__ __forceinline__ void ldsm4(uint32_t* r, uint32_t a) {
    asm volatile("ldmatrix.sync.aligned.m8n8.x4.shared.b16 {%0,%1,%2,%3}, [%4];"
                 : "=r"(r[0]), "=r"(r[1]), "=r"(r[2]), "=r"(r[3]) : "r"(a));
}
__device__ __forceinline__ void mma_f16(float* c, const uint32_t* a, const uint32_t* b) {
    asm volatile(
        "mma.sync.aligned.m16n8k16.row.col.f32.f16.f16.f32 "
        "{%0,%1,%2,%3},{%4,%5,%6,%7},{%8,%9},{%0,%1,%2,%3};\n"
        : "+f"(c[0]), "+f"(c[1]), "+f"(c[2]), "+f"(c[3])
        : "r"(a[0]), "r"(a[1]), "r"(a[2]), "r"(a[3]), "r"(b[0]), "r"(b[1]));
}

// ---------------- quantize helper (fp32 -> fp16, scale folded) ----------------
__device__ __forceinline__ void quant8(const float* __restrict__ src, size_t i,
                                       __half* __restrict__ hi, float scale) {
    float4 v0 = *(const float4*)(src + i);
    float4 v1 = *(const float4*)(src + i + 4);
    float v[8] = {v0.x, v0.y, v0.z, v0.w, v1.x, v1.y, v1.z, v1.w};
#pragma unroll
    for (int j = 0; j < 8; j += 2) {
        __half2 h;
        h.x = __float2half_rn(v[j] * scale);
        h.y = __float2half_rn(v[j + 1] * scale);
        *(__half2*)(hi + i + j) = h;
    }
}

// ===== prep kernel: blocks 0-127 = z (bit-identical SIMT fp32); blocks 128+ = conv =====
// z is FMA-bound (DRAM-idle), conv is DRAM-bound (FMA-idle): co-residency overlaps them.
#define ZROWS 128
#define ZBLOCKS (MROWS / ZROWS)        // 128
#define CBLOCKS 256
#define ZPADF 68
#define ZSMEM ((ZROWS*ZPADF + 64*ZPADF) * (int)sizeof(float))

__global__ __launch_bounds__(512)
void prep_kernel(const float* __restrict__ x, const float* __restrict__ W,
                 const float* __restrict__ A, const float* __restrict__ Bm,
                 const int* __restrict__ kp) {
    const int t = threadIdx.x;

    if (blockIdx.x >= ZBLOCKS) {
        // ---------------- conv path: grid-stride quantize of W, x, B ----------------
        const size_t NW = (size_t)DOUT * DIN / 8;
        const size_t NX = (size_t)MROWS * DIN / 8;
        const size_t NB = (size_t)DOUT * RNK / 8;
        const size_t gstride = (size_t)CBLOCKS * 512;
        for (size_t c = (size_t)(blockIdx.x - ZBLOCKS) * 512 + t; c < NW + NX + NB;
             c += gstride) {
            if (c < NW)            quant8(W,  c * 8,             g_Whi, 1.0f);
            else if (c < NW + NX)  quant8(x,  (c - NW) * 8,      g_Xhi, 1.0f);
            else                   quant8(Bm, (c - NW - NX) * 8, g_Bs,  2.0f);
        }
        return;
    }

    // ---------------- z path: bit-identical to r15 ----------------
    extern __shared__ float zdyn[];
    float (*Xs)[ZPADF] = (float(*)[ZPADF])zdyn;                   // [m][k]
    float (*At)[ZPADF] = (float(*)[ZPADF])(zdyn + ZROWS * ZPADF); // [k][r]
    const int mb = blockIdx.x * ZROWS;
    float acc[4][4];
#pragma unroll
    for (int i = 0; i < 4; i++)
#pragma unroll
        for (int j = 0; j < 4; j++) acc[i][j] = 0.0f;

    const int m0 = (t >> 4) << 2;   // 0..124 step 4
    const int r0 = (t & 15) << 2;   // 0..60  step 4

    for (int kk = 0; kk < DIN; kk += 64) {
        {
            const int row = t >> 2, cb = (t & 3) << 4;
#pragma unroll
            for (int i = 0; i < 4; i++) {
                float4 v = *(const float4*)(x + (size_t)(mb + row) * DIN + kk + cb + i * 4);
                *(float4*)&Xs[row][cb + i * 4] = v;
            }
        }
        {
            const int row = t >> 3, cb = (t & 7) << 3;
#pragma unroll
            for (int i = 0; i < 2; i++) {
                float4 w = *(const float4*)(A + (size_t)row * DIN + kk + cb + i * 4);
                At[cb + i * 4 + 0][row] = w.x;
                At[cb + i * 4 + 1][row] = w.y;
                At[cb + i * 4 + 2][row] = w.z;
                At[cb + i * 4 + 3][row] = w.w;
            }
        }
        __syncthreads();
#pragma unroll 4
        for (int k2 = 0; k2 < 64; k2 += 4) {
            float4 xa[4], av[4];
#pragma unroll
            for (int i = 0; i < 4; i++) xa[i] = *(const float4*)&Xs[m0 + i][k2];
#pragma unroll
            for (int c = 0; c < 4; c++) av[c] = *(const float4*)&At[k2 + c][r0];
            // ascending-k FMA chain (bit-identical ordering to prior rounds)
#pragma unroll
            for (int i = 0; i < 4; i++) {
                acc[i][0] = fmaf(xa[i].x, av[0].x, acc[i][0]);
                acc[i][1] = fmaf(xa[i].x, av[0].y, acc[i][1]);
                acc[i][2] = fmaf(xa[i].x, av[0].z, acc[i][2]);
                acc[i][3] = fmaf(xa[i].x, av[0].w, acc[i][3]);
                acc[i][0] = fmaf(xa[i].y, av[1].x, acc[i][0]);
                acc[i][1] = fmaf(xa[i].y, av[1].y, acc[i][1]);
                acc[i][2] = fmaf(xa[i].y, av[1].z, acc[i][2]);
                acc[i][3] = fmaf(xa[i].y, av[1].w, acc[i][3]);
                acc[i][0] = fmaf(xa[i].z, av[2].x, acc[i][0]);
                acc[i][1] = fmaf(xa[i].z, av[2].y, acc[i][1]);
                acc[i][2] = fmaf(xa[i].z, av[2].z, acc[i][2]);
                acc[i][3] = fmaf(xa[i].z, av[2].w, acc[i][3]);
                acc[i][0] = fmaf(xa[i].w, av[3].x, acc[i][0]);
                acc[i][1] = fmaf(xa[i].w, av[3].y, acc[i][1]);
                acc[i][2] = fmaf(xa[i].w, av[3].z, acc[i][2]);
                acc[i][3] = fmaf(xa[i].w, av[3].w, acc[i][3]);
            }
        }
        __syncthreads();
    }

    // stash z (reuse Xs region), top-k mask, fp16 quantize
#pragma unroll
    for (int i = 0; i < 4; i++)
#pragma unroll
        for (int j = 0; j < 4; j++) Xs[m0 + i][r0 + j] = acc[i][j];
    __syncthreads();

    const int kkeep = *kp;
#pragma unroll
    for (int e = 0; e < 16; e++) {
        int idx = e * 512 + t;              // 128*64 = 8192 entries
        int row = idx >> 6, rr = idx & 63;
        float zv = Xs[row][rr];
        float az = fabsf(zv);
        int cnt = 0;
#pragma unroll
        for (int j = 0; j < 64; j++) cnt += (fabsf(Xs[row][j]) > az) ? 1 : 0;
        float zm = (cnt < kkeep) ? zv : 0.0f;   // matches az >= thresh incl. ties
        g_Zhi[(size_t)(mb + row) * RNK + rr] = __float2half_rn(zm);
    }
}

// ===== main GEMM (r13-proven optimum): 1-pass, 512 thr, 32x64 tiles, BK=64 =====
__device__ __forceinline__ void issue_stage(uint32_t stg, int bm, int bn, int i, int t) {
    const __half *pah, *pbh;
    int stride;
    if (i < NIT_MAIN) {
        const int kk = i * BK;
        pah = g_Xhi + (size_t)bm * DIN + kk;
        pbh = g_Whi + (size_t)bn * DIN + kk;
        stride = DIN;
    } else {
        pah = g_Zhi + (size_t)bm * RNK;
        pbh = g_Bs + (size_t)bn * RNK;
        stride = RNK;
    }
    // X tile: 128 rows x 8 16B-chunks = 1024 positions (2 per thread)
#pragma unroll
    for (int j = 0; j < 2; j++) {
        const int idx = t + j * 512;
        const int row = idx >> 3, part = idx & 7;
        const uint32_t d = (uint32_t)(row * PADK + part * 8) * 2;
        const size_t s = (size_t)row * stride + part * 8;
        cp16s(stg + d, pah + s);
    }
    // W tile: 256 rows x 8 chunks = 2048 positions (4 per thread)
#pragma unroll
    for (int j = 0; j < 4; j++) {
        const int idx = t + j * 512;
        const int row = idx >> 3, part = idx & 7;
        const uint32_t d = (uint32_t)(row * PADK + part * 8) * 2;
        const size_t s = (size_t)row * stride + part * 8;
        cp16s(stg + XT_BYTES + d, pbh + s);
    }
}

__global__ __launch_bounds__(512, 1)
void gemm_kernel(const float* __restrict__ bias, float* __restrict__ out) {
    extern __shared__ __half smem[];
    const uint32_t sb = sptr(smem);
    const int t = threadIdx.x;
    const int warp = t >> 5, lane = t & 31;
    const int wm = warp & 3, wn = warp >> 2;   // 4x4 grid -> 32x64 warp tile
    const int bm = (int)blockIdx.y * BM, bn = (int)blockIdx.x * BN;

    float acc[2][8][4];
#pragma unroll
    for (int a = 0; a < 2; a++)
#pragma unroll
        for (int b = 0; b < 8; b++)
#pragma unroll
            for (int c = 0; c < 4; c++) acc[a][b][c] = 0.0f;

#pragma unroll
    for (int i = 0; i < NSTAGE - 1; i++) {
        issue_stage(sb + i * STG_BYTES, bm, bn, i, t);
        cp_commit();
    }

    for (int i = 0; i < NIT; i++) {
        cp_wait<NSTAGE - 2>();       // stage i complete (always-commit discipline)
        __syncthreads();
        const uint32_t stg = sb + (i % NSTAGE) * STG_BYTES;
        const uint32_t sX = stg;
        const uint32_t sW = stg + XT_BYTES;
#pragma unroll
        for (int ks = 0; ks < 4; ks++) {
            uint32_t ah[2][4], bh[4][4];
            const int arow = wm * 32 + (lane & 15);
            const int acol = ks * 16 + (lane >> 4) * 8;
#pragma unroll
            for (int mt = 0; mt < 2; mt++) {
                const uint32_t off = (uint32_t)((arow + mt * 16) * PADK + acol) * 2;
                ldsm4(ah[mt], sX + off);
            }
            const int brow0 = wn * 64 + ((lane >> 4) << 3) + (lane & 7);
            const int bcol = ks * 16 + (((lane >> 3) & 1) << 3);
#pragma unroll
            for (int np = 0; np < 4; np++) {
                const uint32_t off = (uint32_t)((brow0 + np * 16) * PADK + bcol) * 2;
                ldsm4(bh[np], sW + off);
            }
#pragma unroll
            for (int mt = 0; mt < 2; mt++)
#pragma unroll
                for (int nt = 0; nt < 8; nt++)
                    mma_f16(acc[mt][nt], ah[mt], &bh[nt >> 1][(nt & 1) * 2]);
        }
        if (i + NSTAGE - 1 < NIT)
            issue_stage(sb + ((i + NSTAGE - 1) % NSTAGE) * STG_BYTES, bm, bn,
                        i + NSTAGE - 1, t);
        cp_commit();                 // always commit (possibly empty) for group accounting
    }

    // epilogue: + bias, store fp32
    const int gr = lane >> 2, gc = (lane & 3) * 2;
#pragma unroll
    for (int mt = 0; mt < 2; mt++) {
#pragma unroll
        for (int nt = 0; nt < 8; nt++) {
            int row = bm + wm * 32 + mt * 16 + gr;
            int col = bn + wn * 64 + nt * 8 + gc;
            float2 bv = *(const float2*)(bias + col);
            float2 o0, o1;
            o0.x = acc[mt][nt][0] + bv.x;
            o0.y = acc[mt][nt][1] + bv.y;
            o1.x = acc[mt][nt][2] + bv.x;
            o1.y = acc[mt][nt][3] + bv.y;
            *(float2*)(out + (size_t)row * DOUT + col) = o0;
            *(float2*)(out + (size_t)(row + 8) * DOUT + col) = o1;
        }
    }
}

// ---------------- launch ----------------
extern "C" void kernel_launch(void* const* d_in, const int* in_sizes, int n_in,
                              void* d_out, int out_size) {
    const float* x = (const float*)d_in[0];
    const float* W = (const float*)d_in[1];
    const float* b = (const float*)d_in[2];
    const float* A = (const float*)d_in[3];
    const float* B = (const float*)d_in[4];
    const int*   k = (const int*)d_in[5];
    float* out = (float*)d_out;
    (void)in_sizes; (void)n_in; (void)out_size;

    // launch 1: fused prep — z blocks (FMA-bound) + conv blocks (DRAM-bound) co-resident
    cudaFuncSetAttribute(prep_kernel, cudaFuncAttributeMaxDynamicSharedMemorySize, ZSMEM);
    prep_kernel<<<ZBLOCKS + CBLOCKS, 512, ZSMEM>>>(x, W, A, B, k);

    // launch 2: fused main GEMM (r13 optimum; 65 iters, single-limb z tail)
    cudaFuncSetAttribute(gemm_kernel, cudaFuncAttributeMaxDynamicSharedMemorySize,
                         NSTAGE * STG_BYTES);
    gemm_kernel<<<dim3(DOUT / BN, MROWS / BM), 512, NSTAGE * STG_BYTES>>>(b, out);
}

// round 17
// speedup vs baseline: 1.1221x; 1.1221x over previous
#include <cuda_runtime.h>
#include <cuda_fp16.h>
#include <cstdint>

#define DIN   4096
#define DOUT  4096
#define MROWS 16384
#define RNK   64

#define BM 128
#define BN 256
#define BK 64
#define PADK 72                        // fp16 elems per smem row (144B), ldmatrix conflict-free
#define XT_BYTES (BM*PADK*2)           // 18432 B
#define WT_BYTES (BN*PADK*2)           // 36864 B
#define STG_BYTES (XT_BYTES + WT_BYTES)    // 55296 B per stage
#define NSTAGE 3
#define NIT_MAIN (DIN/BK)              // 64
#define NIT (NIT_MAIN + 1)             // 65: 64 main + 1 LoRA (fp16 z single limb)

// ---------------- scratch (static device globals; no allocation) ----------------
__device__ __half g_Whi[(size_t)DOUT*DIN];     // fp16(W)
__device__ __half g_Xhi[(size_t)MROWS*DIN];    // fp16(x)   (written by z kernel)
__device__ __half g_Bs [(size_t)DOUT*RNK];     // fp16(2*B) (SCALE folded)
__device__ __half g_Zhi[(size_t)MROWS*RNK];    // fp16(masked z)

// ---------------- PTX helpers ----------------
__device__ __forceinline__ uint32_t sptr(const void* p) {
    return (uint32_t)__cvta_generic_to_shared(p);
}
__device__ __forceinline__ void cp16s(uint32_t dst, const void* src) {
    asm volatile("cp.async.cg.shared.global [%0], [%1], 16;" :: "r"(dst), "l"(src));
}
__device__ __forceinline__ void cp_commit() { asm volatile("cp.async.commit_group;" ::); }
template <int N> __device__ __forceinline__ void cp_wait() {
    asm volatile("cp.async.wait_group %0;" :: "n"(N));
}
__device__ __forceinline__ void ldsm4(uint32_t* r, uint32_t a) {
    asm volatile("ldmatrix.sync.aligned.m8n8.x4.shared.b16 {%0,%1,%2,%3}, [%4];"
                 : "=r"(r[0]), "=r"(r[1]), "=r"(r[2]), "=r"(r[3]) : "r"(a));
}
__device__ __forceinline__ void mma_f16(float* c, const uint32_t* a, const uint32_t* b) {
    asm volatile(
        "mma.sync.aligned.m16n8k16.row.col.f32.f16.f16.f32 "
        "{%0,%1,%2,%3},{%4,%5,%6,%7},{%8,%9},{%0,%1,%2,%3};\n"
        : "+f"(c[0]), "+f"(c[1]), "+f"(c[2]), "+f"(c[3])
        : "r"(a[0]), "r"(a[1]), "r"(a[2]), "r"(a[3]), "r"(b[0]), "r"(b[1]));
}

// ---------------- quantize helper (fp32 -> fp16, scale folded) ----------------
__device__ __forceinline__ void quant8(const float* __restrict__ src, size_t i,
                                       __half* __restrict__ hi, float scale) {
    float4 v0 = *(const float4*)(src + i);
    float4 v1 = *(const float4*)(src + i + 4);
    float v[8] = {v0.x, v0.y, v0.z, v0.w, v1.x, v1.y, v1.z, v1.w};
#pragma unroll
    for (int j = 0; j < 8; j += 2) {
        __half2 h;
        h.x = __float2half_rn(v[j] * scale);
        h.y = __float2half_rn(v[j + 1] * scale);
        *(__half2*)(hi + i + j) = h;
    }
}
#define WBLK ((DOUT*DIN)/(256*8))              // 8192
#define BBLK ((DOUT*RNK)/(256*8))              // 128

// conv: W and B only (x is quantized inside the z kernel, which already reads it)
__global__ __launch_bounds__(256) void conv_wb_kernel(const float* __restrict__ W,
                                                      const float* __restrict__ Bm) {
    const int b = blockIdx.x;
    if (b < WBLK) {
        size_t i = ((size_t)b * 256 + threadIdx.x) * 8;
        quant8(W, i, g_Whi, 1.0f);
    } else {
        size_t i = ((size_t)(b - WBLK) * 256 + threadIdx.x) * 8;
        quant8(Bm, i, g_Bs, 2.0f /* ALPHA/R */);
    }
}

// ===== z kernel: bit-identical SIMT fp32 z + fused x-quantization at load time =====
#define ZROWS 128
#define ZPADF 68
#define ZSMEM ((ZROWS*ZPADF + 64*ZPADF) * (int)sizeof(float))

__global__ __launch_bounds__(512, 1)
void z_topk_kernel(const float* __restrict__ x, const float* __restrict__ A,
                   const int* __restrict__ kp) {
    extern __shared__ float zdyn[];
    float (*Xs)[ZPADF] = (float(*)[ZPADF])zdyn;                   // [m][k]
    float (*At)[ZPADF] = (float(*)[ZPADF])(zdyn + ZROWS * ZPADF); // [k][r]
    const int t = threadIdx.x;
    const int mb = blockIdx.x * ZROWS;
    float acc[4][4];
#pragma unroll
    for (int i = 0; i < 4; i++)
#pragma unroll
        for (int j = 0; j < 4; j++) acc[i][j] = 0.0f;

    const int m0 = (t >> 4) << 2;   // 0..124 step 4
    const int r0 = (t & 15) << 2;   // 0..60  step 4

    for (int kk = 0; kk < DIN; kk += 64) {
        // X: load 128x64 tile; simultaneously quantize-store to g_Xhi (fused conv)
        {
            const int row = t >> 2, cb = (t & 3) << 4;
#pragma unroll
            for (int i = 0; i < 4; i++) {
                const size_t gofs = (size_t)(mb + row) * DIN + kk + cb + i * 4;
                float4 v = *(const float4*)(x + gofs);
                *(float4*)&Xs[row][cb + i * 4] = v;
                __half2 h0, h1;
                h0.x = __float2half_rn(v.x);
                h0.y = __float2half_rn(v.y);
                h1.x = __float2half_rn(v.z);
                h1.y = __float2half_rn(v.w);
                *(__half2*)(g_Xhi + gofs)     = h0;
                *(__half2*)(g_Xhi + gofs + 2) = h1;
            }
        }
        // A: 64x64 tile, transposed store
        {
            const int row = t >> 3, cb = (t & 7) << 3;
#pragma unroll
            for (int i = 0; i < 2; i++) {
                float4 w = *(const float4*)(A + (size_t)row * DIN + kk + cb + i * 4);
                At[cb + i * 4 + 0][row] = w.x;
                At[cb + i * 4 + 1][row] = w.y;
                At[cb + i * 4 + 2][row] = w.z;
                At[cb + i * 4 + 3][row] = w.w;
            }
        }
        __syncthreads();
#pragma unroll 4
        for (int k2 = 0; k2 < 64; k2 += 4) {
            float4 xa[4], av[4];
#pragma unroll
            for (int i = 0; i < 4; i++) xa[i] = *(const float4*)&Xs[m0 + i][k2];
#pragma unroll
            for (int c = 0; c < 4; c++) av[c] = *(const float4*)&At[k2 + c][r0];
            // ascending-k FMA chain (bit-identical ordering to prior rounds)
#pragma unroll
            for (int i = 0; i < 4; i++) {
                acc[i][0] = fmaf(xa[i].x, av[0].x, acc[i][0]);
                acc[i][1] = fmaf(xa[i].x, av[0].y, acc[i][1]);
                acc[i][2] = fmaf(xa[i].x, av[0].z, acc[i][2]);
                acc[i][3] = fmaf(xa[i].x, av[0].w, acc[i][3]);
                acc[i][0] = fmaf(xa[i].y, av[1].x, acc[i][0]);
                acc[i][1] = fmaf(xa[i].y, av[1].y, acc[i][1]);
                acc[i][2] = fmaf(xa[i].y, av[1].z, acc[i][2]);
                acc[i][3] = fmaf(xa[i].y, av[1].w, acc[i][3]);
                acc[i][0] = fmaf(xa[i].z, av[2].x, acc[i][0]);
                acc[i][1] = fmaf(xa[i].z, av[2].y, acc[i][1]);
                acc[i][2] = fmaf(xa[i].z, av[2].z, acc[i][2]);
                acc[i][3] = fmaf(xa[i].z, av[2].w, acc[i][3]);
                acc[i][0] = fmaf(xa[i].w, av[3].x, acc[i][0]);
                acc[i][1] = fmaf(xa[i].w, av[3].y, acc[i][1]);
                acc[i][2] = fmaf(xa[i].w, av[3].z, acc[i][2]);
                acc[i][3] = fmaf(xa[i].w, av[3].w, acc[i][3]);
            }
        }
        __syncthreads();
    }

    // stash z (reuse Xs region), top-k mask, fp16 quantize
#pragma unroll
    for (int i = 0; i < 4; i++)
#pragma unroll
        for (int j = 0; j < 4; j++) Xs[m0 + i][r0 + j] = acc[i][j];
    __syncthreads();

    const int kkeep = *kp;
#pragma unroll
    for (int e = 0; e < 16; e++) {
        int idx = e * 512 + t;              // 128*64 = 8192 entries
        int row = idx >> 6, rr = idx & 63;
        float zv = Xs[row][rr];
        float az = fabsf(zv);
        int cnt = 0;
#pragma unroll
        for (int j = 0; j < 64; j++) cnt += (fabsf(Xs[row][j]) > az) ? 1 : 0;
        float zm = (cnt < kkeep) ? zv : 0.0f;   // matches az >= thresh incl. ties
        g_Zhi[(size_t)(mb + row) * RNK + rr] = __float2half_rn(zm);
    }
}

// ===== main GEMM (r13-proven optimum): 1-pass, 512 thr, 32x64 tiles, BK=64, 65 iters =====
__device__ __forceinline__ void issue_stage(uint32_t stg, int bm, int bn, int i, int t) {
    const __half *pah, *pbh;
    int stride;
    if (i < NIT_MAIN) {
        const int kk = i * BK;
        pah = g_Xhi + (size_t)bm * DIN + kk;
        pbh = g_Whi + (size_t)bn * DIN + kk;
        stride = DIN;
    } else {
        pah = g_Zhi + (size_t)bm * RNK;
        pbh = g_Bs + (size_t)bn * RNK;
        stride = RNK;
    }
    // X tile: 128 rows x 8 16B-chunks = 1024 positions (2 per thread)
#pragma unroll
    for (int j = 0; j < 2; j++) {
        const int idx = t + j * 512;
        const int row = idx >> 3, part = idx & 7;
        const uint32_t d = (uint32_t)(row * PADK + part * 8) * 2;
        const size_t s = (size_t)row * stride + part * 8;
        cp16s(stg + d, pah + s);
    }
    // W tile: 256 rows x 8 chunks = 2048 positions (4 per thread)
#pragma unroll
    for (int j = 0; j < 4; j++) {
        const int idx = t + j * 512;
        const int row = idx >> 3, part = idx & 7;
        const uint32_t d = (uint32_t)(row * PADK + part * 8) * 2;
        const size_t s = (size_t)row * stride + part * 8;
        cp16s(stg + XT_BYTES + d, pbh + s);
    }
}

__global__ __launch_bounds__(512, 1)
void gemm_kernel(const float* __restrict__ bias, float* __restrict__ out) {
    extern __shared__ __half smem[];
    const uint32_t sb = sptr(smem);
    const int t = threadIdx.x;
    const int warp = t >> 5, lane = t & 31;
    const int wm = warp & 3, wn = warp >> 2;   // 4x4 grid -> 32x64 warp tile
    const int bm = (int)blockIdx.y * BM, bn = (int)blockIdx.x * BN;

    float acc[2][8][4];
#pragma unroll
    for (int a = 0; a < 2; a++)
#pragma unroll
        for (int b = 0; b < 8; b++)
#pragma unroll
            for (int c = 0; c < 4; c++) acc[a][b][c] = 0.0f;

#pragma unroll
    for (int i = 0; i < NSTAGE - 1; i++) {
        issue_stage(sb + i * STG_BYTES, bm, bn, i, t);
        cp_commit();
    }

    for (int i = 0; i < NIT; i++) {
        cp_wait<NSTAGE - 2>();       // stage i complete (always-commit discipline)
        __syncthreads();
        const uint32_t stg = sb + (i % NSTAGE) * STG_BYTES;
        const uint32_t sX = stg;
        const uint32_t sW = stg + XT_BYTES;
#pragma unroll
        for (int ks = 0; ks < 4; ks++) {
            uint32_t ah[2][4], bh[4][4];
            const int arow = wm * 32 + (lane & 15);
            const int acol = ks * 16 + (lane >> 4) * 8;
#pragma unroll
            for (int mt = 0; mt < 2; mt++) {
                const uint32_t off = (uint32_t)((arow + mt * 16) * PADK + acol) * 2;
                ldsm4(ah[mt], sX + off);
            }
            const int brow0 = wn * 64 + ((lane >> 4) << 3) + (lane & 7);
            const int bcol = ks * 16 + (((lane >> 3) & 1) << 3);
#pragma unroll
            for (int np = 0; np < 4; np++) {
                const uint32_t off = (uint32_t)((brow0 + np * 16) * PADK + bcol) * 2;
                ldsm4(bh[np], sW + off);
            }
#pragma unroll
            for (int mt = 0; mt < 2; mt++)
#pragma unroll
                for (int nt = 0; nt < 8; nt++)
                    mma_f16(acc[mt][nt], ah[mt], &bh[nt >> 1][(nt & 1) * 2]);
        }
        if (i + NSTAGE - 1 < NIT)
            issue_stage(sb + ((i + NSTAGE - 1) % NSTAGE) * STG_BYTES, bm, bn,
                        i + NSTAGE - 1, t);
        cp_commit();                 // always commit (possibly empty) for group accounting
    }

    // epilogue: + bias, store fp32
    const int gr = lane >> 2, gc = (lane & 3) * 2;
#pragma unroll
    for (int mt = 0; mt < 2; mt++) {
#pragma unroll
        for (int nt = 0; nt < 8; nt++) {
            int row = bm + wm * 32 + mt * 16 + gr;
            int col = bn + wn * 64 + nt * 8 + gc;
            float2 bv = *(const float2*)(bias + col);
            float2 o0, o1;
            o0.x = acc[mt][nt][0] + bv.x;
            o0.y = acc[mt][nt][1] + bv.y;
            o1.x = acc[mt][nt][2] + bv.x;
            o1.y = acc[mt][nt][3] + bv.y;
            *(float2*)(out + (size_t)row * DOUT + col) = o0;
            *(float2*)(out + (size_t)(row + 8) * DOUT + col) = o1;
        }
    }
}

// ---------------- launch ----------------
extern "C" void kernel_launch(void* const* d_in, const int* in_sizes, int n_in,
                              void* d_out, int out_size) {
    const float* x = (const float*)d_in[0];
    const float* W = (const float*)d_in[1];
    const float* b = (const float*)d_in[2];
    const float* A = (const float*)d_in[3];
    const float* B = (const float*)d_in[4];
    const int*   k = (const int*)d_in[5];
    float* out = (float*)d_out;
    (void)in_sizes; (void)n_in; (void)out_size;

    // launch 1: quantize W and B (x is handled inside the z kernel)
    conv_wb_kernel<<<WBLK + BBLK, 256>>>(W, B);

    // launch 2: z = x@A^T exact SIMT fp32 + fused x-quantization
    cudaFuncSetAttribute(z_topk_kernel, cudaFuncAttributeMaxDynamicSharedMemorySize, ZSMEM);
    z_topk_kernel<<<MROWS / ZROWS, 512, ZSMEM>>>(x, A, k);

    // launch 3: fused main GEMM (r13 optimum; 65 iters, single-limb z tail)
    cudaFuncSetAttribute(gemm_kernel, cudaFuncAttributeMaxDynamicSharedMemorySize,
                         NSTAGE * STG_BYTES);
    gemm_kernel<<<dim3(DOUT / BN, MROWS / BM), 512, NSTAGE * STG_BYTES>>>(b, out);
}